// round 5
// baseline (speedup 1.0000x reference)
#include <cuda_runtime.h>
#include <cuda_bf16.h>
#include <cstdint>

// ---------------------------------------------------------------------------
// STDP delta_w on GB300 — base-sm_103-legal tensor core path (mma.sync bf16).
//
//   trace_t = 0.5*trace_{t-1} + in_t
//   dw[o,i] = sum_{t,b} trace[t,b,i] * out[t,b,o]
//
// R4: 2 timesteps per iteration (K=64 per MMA phase), halving barriers and
// doubling the latency-hiding window. cp.async staging depth = 4 steps.
// ---------------------------------------------------------------------------

#define T_STEPS 2048
#define B_DIM   128
#define N_IN    256
#define N_OUT   128
#define CHUNK   64
#define NIT     (CHUNK / 2)         // 32 iterations, 2 steps each
#define GT      (T_STEPS / CHUNK)   // 32
#define KB      32
#define NBS     (B_DIM / KB)        // 4
#define WARMUP  16                  // 0.5^16 ~ 1.5e-5 truncation
#define NTHR    512

// Dynamic smem layout (bytes):
//   [0, 131072)        fp32 `in` staging: 2 bufs x (2 steps x 32KB)
//   [131072, 196608)   trace bf16 tile: 2 bufs x 32KB (64 rows x 512B, swizzled)
//   [196608, 229376)   out   bf16 tile: 2 bufs x 16KB (64 rows x 256B, swizzled)
#define SI_OFF   0
#define SI_STEP  32768
#define SI_BSZ   65536
#define TR_OFF   131072
#define TR_BSZ   32768
#define TR_STEP  16384
#define OT_OFF   196608
#define OT_BSZ   16384
#define OT_STEP  8192
#define SM_TOTAL 229376

#define IN_SLAB  (B_DIM * N_IN  * 4)   // bytes per timestep of gin
#define OUT_SLAB (B_DIM * N_OUT / 4)   // float4 per timestep of gout

__device__ __forceinline__ uint32_t smem_u32(const void* p) {
    uint32_t a;
    asm("{ .reg .u64 t; cvta.to.shared.u64 t, %1; cvt.u32.u64 %0, t; }" : "=r"(a) : "l"(p));
    return a;
}

__device__ __forceinline__ void cp16(uint32_t s, const void* g) {
    asm volatile("cp.async.cg.shared.global [%0], [%1], 16;" :: "r"(s), "l"(g) : "memory");
}
#define CP_COMMIT() asm volatile("cp.async.commit_group;" ::: "memory")
#define CP_WAIT1()  asm volatile("cp.async.wait_group 1;" ::: "memory")

__device__ __forceinline__ void ldsm4t(uint32_t* d, uint32_t a) {
    asm volatile("ldmatrix.sync.aligned.m8n8.x4.trans.shared.b16 {%0,%1,%2,%3}, [%4];"
                 : "=r"(d[0]), "=r"(d[1]), "=r"(d[2]), "=r"(d[3]) : "r"(a));
}

__device__ __forceinline__ void mma16816(float* d, const uint32_t* a, const uint32_t* b) {
    asm volatile(
        "mma.sync.aligned.m16n8k16.row.col.f32.bf16.bf16.f32 "
        "{%0,%1,%2,%3},{%4,%5,%6,%7},{%8,%9},{%0,%1,%2,%3};"
        : "+f"(d[0]), "+f"(d[1]), "+f"(d[2]), "+f"(d[3])
        : "r"(a[0]), "r"(a[1]), "r"(a[2]), "r"(a[3]), "r"(b[0]), "r"(b[1]));
}

__device__ __forceinline__ uint32_t pack_bf16x2(float x, float y) {
    __nv_bfloat162 h = __float22bfloat162_rn(make_float2(x, y));
    return *reinterpret_cast<uint32_t*>(&h);
}

__global__ void stdp_zero_kernel(float* __restrict__ p, int n) {
    int i = blockIdx.x * blockDim.x + threadIdx.x;
    if (i < n) p[i] = 0.0f;
}

__global__ void __launch_bounds__(NTHR, 1)
stdp_main_kernel(const float* __restrict__ gin,   // [T, B, N_IN]
                 const float* __restrict__ gout,  // [T, B, N_OUT]
                 float* __restrict__ dw)          // [N_OUT, N_IN]
{
    extern __shared__ __align__(1024) char smem[];
    const uint32_t sb = smem_u32(smem);
    const int tid = threadIdx.x;
    const int w   = tid >> 5;
    const int l   = tid & 31;

    const int t0 = blockIdx.x * CHUNK;
    const int b0 = blockIdx.y * KB;

    // ---- per-thread offsets -------------------------------------------------
    // in:  f = tid + 512q, q<4;  b = f>>6, i = (f&63)*4
    // out: f = tid + 512q, q<2;  b = f>>5, o = (f&31)*4
    int gi_off[4];          // byte offset within one timestep's in slab
    uint32_t si_slot[4];    // staging slot within one step's staging area
    uint32_t sts_in[4];     // swizzled bf16 STS offset within one step's rows
#pragma unroll
    for (int q = 0; q < 4; q++) {
        int f  = tid + 512 * q;
        int bl = f >> 6;
        int i4 = (f & 63) << 2;
        gi_off[q]  = ((b0 + bl) * (N_IN / 4) + (f & 63)) * 16;
        si_slot[q] = (uint32_t)(f * 16);
        sts_in[q]  = (uint32_t)(bl * 512 + (((i4 >> 3) ^ (bl & 7)) << 4) + ((i4 & 7) << 1));
    }
    int go_off[2]; uint32_t sts_out[2];
#pragma unroll
    for (int q = 0; q < 2; q++) {
        int f  = tid + 512 * q;
        int bl = f >> 5;
        int o4 = (f & 31) << 2;
        go_off[q]  = (b0 + bl) * (N_OUT / 4) + (f & 31);
        sts_out[q] = (uint32_t)(bl * 256 + (((o4 >> 3) ^ (bl & 7)) << 4) + ((o4 & 7) << 1));
    }

    // ---- ldmatrix source addresses (relative to tile buf base) --------------
    // Tile rows r = st*32 + b; (r & 7) == (b & 7), so per-step blocks are
    // byte-offset copies of the R3 layout at st*{TR,OT}_STEP.
    const int wr = w >> 2, wc = w & 3;
    const int obase = wr * 32, ibase = wc * 64;

    uint32_t a_addr[2];
#pragma unroll
    for (int mt = 0; mt < 2; mt++) {
        int b  = (l & 7) + ((l >> 4) << 3);
        int ch = ((obase + mt * 16) >> 3) + ((l >> 3) & 1);
        a_addr[mt] = (uint32_t)(b * 256 + ((ch ^ (b & 7)) << 4));
    }
    uint32_t b_addr[4];
#pragma unroll
    for (int np = 0; np < 4; np++) {
        int b  = (l & 7) + (((l >> 3) & 1) << 3);
        int ch = ((ibase + np * 16) >> 3) + ((l >> 4) & 1);
        b_addr[np] = (uint32_t)(b * 512 + ((ch ^ (b & 7)) << 4));
    }

    // ---- stage iterations 0 and 1 (4 timesteps) via cp.async ----------------
#pragma unroll
    for (int p = 0; p < 2; p++) {
#pragma unroll
        for (int st = 0; st < 2; st++) {
            const char* src = (const char*)gin + (size_t)(t0 + 2 * p + st) * IN_SLAB;
#pragma unroll
            for (int q = 0; q < 4; q++)
                cp16(sb + SI_OFF + p * SI_BSZ + st * SI_STEP + si_slot[q], src + gi_off[q]);
        }
        CP_COMMIT();
    }

    // ---- trace warm-up ------------------------------------------------------
    float4 tr4[4];
#pragma unroll
    for (int q = 0; q < 4; q++) tr4[q] = make_float4(0.f, 0.f, 0.f, 0.f);

    int tw0 = t0 - WARMUP; if (tw0 < 0) tw0 = 0;
#pragma unroll 2
    for (int t = tw0; t < t0; t++) {
        const char* src = (const char*)gin + (size_t)t * IN_SLAB;
#pragma unroll
        for (int q = 0; q < 4; q++) {
            float4 v = *reinterpret_cast<const float4*>(src + gi_off[q]);
            tr4[q].x = fmaf(0.5f, tr4[q].x, v.x);
            tr4[q].y = fmaf(0.5f, tr4[q].y, v.y);
            tr4[q].z = fmaf(0.5f, tr4[q].z, v.z);
            tr4[q].w = fmaf(0.5f, tr4[q].w, v.w);
        }
    }

    float acc[2][8][4];
#pragma unroll
    for (int mt = 0; mt < 2; mt++)
#pragma unroll
        for (int nt = 0; nt < 8; nt++)
#pragma unroll
            for (int r = 0; r < 4; r++) acc[mt][nt][r] = 0.0f;

    // out: one-iteration (2-step) register prefetch
    float4 vo[2][2];
    {
        const float4* po = reinterpret_cast<const float4*>(gout) + (size_t)t0 * OUT_SLAB;
#pragma unroll
        for (int st = 0; st < 2; st++)
#pragma unroll
            for (int q = 0; q < 2; q++) vo[st][q] = po[st * OUT_SLAB + go_off[q]];
    }

    // ---- main loop: ONE barrier per 2 timesteps -----------------------------
    for (int it = 0; it < NIT; it++) {
        const uint32_t buf = it & 1;

        CP_WAIT1();   // staging for this iteration complete (self-filled slots)

        // trace update + convert + swizzled STS for both steps
#pragma unroll
        for (int st = 0; st < 2; st++) {
            const char* sg = smem + buf * SI_BSZ + st * SI_STEP;
            char* td = smem + TR_OFF + buf * TR_BSZ + st * TR_STEP;
#pragma unroll
            for (int q = 0; q < 4; q++) {
                float4 v = *reinterpret_cast<const float4*>(sg + si_slot[q]);
                tr4[q].x = fmaf(0.5f, tr4[q].x, v.x);
                tr4[q].y = fmaf(0.5f, tr4[q].y, v.y);
                tr4[q].z = fmaf(0.5f, tr4[q].z, v.z);
                tr4[q].w = fmaf(0.5f, tr4[q].w, v.w);
                uint2 u = make_uint2(pack_bf16x2(tr4[q].x, tr4[q].y),
                                     pack_bf16x2(tr4[q].z, tr4[q].w));
                *reinterpret_cast<uint2*>(td + sts_in[q]) = u;
            }
            char* od = smem + OT_OFF + buf * OT_BSZ + st * OT_STEP;
#pragma unroll
            for (int q = 0; q < 2; q++) {
                uint2 u = make_uint2(pack_bf16x2(vo[st][q].x, vo[st][q].y),
                                     pack_bf16x2(vo[st][q].z, vo[st][q].w));
                *reinterpret_cast<uint2*>(od + sts_out[q]) = u;
            }
        }

        // refill this staging buffer with iteration it+2 (slots consumed above)
        if (it + 2 < NIT) {
#pragma unroll
            for (int st = 0; st < 2; st++) {
                const char* src = (const char*)gin
                                + (size_t)(t0 + 2 * (it + 2) + st) * IN_SLAB;
#pragma unroll
                for (int q = 0; q < 4; q++)
                    cp16(sb + SI_OFF + buf * SI_BSZ + st * SI_STEP + si_slot[q],
                         src + gi_off[q]);
            }
        }
        CP_COMMIT();  // unconditional: uniform group accounting

        // prefetch out for iteration it+1
        if (it + 1 < NIT) {
            const float4* po = reinterpret_cast<const float4*>(gout)
                             + (size_t)(t0 + 2 * (it + 1)) * OUT_SLAB;
#pragma unroll
            for (int st = 0; st < 2; st++)
#pragma unroll
                for (int q = 0; q < 2; q++) vo[st][q] = po[st * OUT_SLAB + go_off[q]];
        }

        __syncthreads();

        // MMA phase: K = 64 (four k16 blocks spanning 2 timesteps)
        const uint32_t abase = sb + OT_OFF + buf * OT_BSZ;
        const uint32_t bbase = sb + TR_OFF + buf * TR_BSZ;
#pragma unroll
        for (int kb = 0; kb < 4; kb++) {
            uint32_t af[2][4];
            ldsm4t(af[0], abase + a_addr[0] + kb * 16 * 256);
            ldsm4t(af[1], abase + a_addr[1] + kb * 16 * 256);
#pragma unroll
            for (int np = 0; np < 4; np++) {
                uint32_t bf[4];
                ldsm4t(bf, bbase + b_addr[np] + kb * 16 * 512);
#pragma unroll
                for (int mt = 0; mt < 2; mt++) {
                    mma16816(acc[mt][2 * np],     af[mt], bf);
                    mma16816(acc[mt][2 * np + 1], af[mt], bf + 2);
                }
            }
        }
        // no second barrier: next iteration writes the OTHER tile buffer
    }

    // ---- epilogue: vector reductions into dw --------------------------------
#pragma unroll
    for (int mt = 0; mt < 2; mt++) {
#pragma unroll
        for (int nt = 0; nt < 8; nt++) {
            const int o = obase + mt * 16 + (l >> 2);
            const int i = ibase + nt * 8 + ((l & 3) << 1);
            float* p = dw + (size_t)o * N_IN + i;
            asm volatile("red.global.add.v2.f32 [%0], {%1,%2};"
                         :: "l"(p), "f"(acc[mt][nt][0]), "f"(acc[mt][nt][1]) : "memory");
            asm volatile("red.global.add.v2.f32 [%0], {%1,%2};"
                         :: "l"(p + 8 * N_IN), "f"(acc[mt][nt][2]), "f"(acc[mt][nt][3]) : "memory");
        }
    }
}

extern "C" void kernel_launch(void* const* d_in, const int* in_sizes, int n_in,
                              void* d_out, int out_size) {
    (void)in_sizes; (void)n_in; (void)out_size;
    const float* gin  = (const float*)d_in[0];   // in_spikes  [T, B, N_IN]
    const float* gout = (const float*)d_in[1];   // out_spikes [T, B, N_OUT]
    float* dw = (float*)d_out;                   // [N_OUT, N_IN]

    stdp_zero_kernel<<<(N_OUT * N_IN + NTHR - 1) / NTHR, NTHR>>>(dw, N_OUT * N_IN);

    cudaFuncSetAttribute(stdp_main_kernel,
                         cudaFuncAttributeMaxDynamicSharedMemorySize, SM_TOTAL);
    dim3 grid(GT, NBS);
    stdp_main_kernel<<<grid, NTHR, SM_TOTAL>>>(gin, gout, dw);
}

// round 7
// speedup vs baseline: 1.2208x; 1.2208x over previous
#include <cuda_runtime.h>
#include <cuda_bf16.h>
#include <cstdint>

// ---------------------------------------------------------------------------
// STDP delta_w on GB300 — base-sm_103-legal tensor core path (mma.sync bf16).
//
//   trace_t = 0.5*trace_{t-1} + in_t
//   dw[o,i] = sum_{t,b} trace[t,b,i] * out[t,b,o]
//
// R5: software-pipelined iteration (MMA(s) and produce(s+1) between the same
// barriers, staggered by warp parity), 4-deep cp.async staging ring,
// 37 variable-length time chunks x 4 batch slices = 148 CTAs (full chip).
// ---------------------------------------------------------------------------

#define T_STEPS 2048
#define B_DIM   128
#define N_IN    256
#define N_OUT   128
#define GT      37                  // time chunks (len 55 or 56)
#define KB      32
#define NBS     (B_DIM / KB)        // 4
#define WARMUP  16                  // 0.5^16 ~ 1.5e-5 truncation
#define NTHR    512

// Dynamic smem layout (bytes):
//   [0, 131072)        fp32 `in` staging ring: 4 slots x 32KB
//   [131072, 163840)   trace bf16 tile: 2 bufs x 16KB (32 rows x 512B, swizzled)
//   [163840, 180224)   out   bf16 tile: 2 bufs x  8KB (32 rows x 256B, swizzled)
#define SI_STEP  32768
#define TR_OFF   131072
#define TR_BSZ   16384
#define OT_OFF   163840
#define OT_BSZ   8192
#define SM_TOTAL 180224

#define IN_SLAB  (B_DIM * N_IN  * 4)   // bytes per timestep of gin
#define OUT_SLAB (B_DIM * N_OUT / 4)   // float4 per timestep of gout

__device__ __forceinline__ uint32_t smem_u32(const void* p) {
    uint32_t a;
    asm("{ .reg .u64 t; cvta.to.shared.u64 t, %1; cvt.u32.u64 %0, t; }" : "=r"(a) : "l"(p));
    return a;
}

__device__ __forceinline__ void cp16(uint32_t s, const void* g) {
    asm volatile("cp.async.cg.shared.global [%0], [%1], 16;" :: "r"(s), "l"(g) : "memory");
}
#define CP_COMMIT() asm volatile("cp.async.commit_group;" ::: "memory")
#define CP_WAIT3()  asm volatile("cp.async.wait_group 3;" ::: "memory")

__device__ __forceinline__ void ldsm4t(uint32_t* d, uint32_t a) {
    asm volatile("ldmatrix.sync.aligned.m8n8.x4.trans.shared.b16 {%0,%1,%2,%3}, [%4];"
                 : "=r"(d[0]), "=r"(d[1]), "=r"(d[2]), "=r"(d[3]) : "r"(a));
}

__device__ __forceinline__ void mma16816(float* d, const uint32_t* a, const uint32_t* b) {
    asm volatile(
        "mma.sync.aligned.m16n8k16.row.col.f32.bf16.bf16.f32 "
        "{%0,%1,%2,%3},{%4,%5,%6,%7},{%8,%9},{%0,%1,%2,%3};"
        : "+f"(d[0]), "+f"(d[1]), "+f"(d[2]), "+f"(d[3])
        : "r"(a[0]), "r"(a[1]), "r"(a[2]), "r"(a[3]), "r"(b[0]), "r"(b[1]));
}

__device__ __forceinline__ uint32_t pack_bf16x2(float x, float y) {
    __nv_bfloat162 h = __float22bfloat162_rn(make_float2(x, y));
    return *reinterpret_cast<uint32_t*>(&h);
}

__global__ void stdp_zero_kernel(float* __restrict__ p, int n) {
    int i = blockIdx.x * blockDim.x + threadIdx.x;
    if (i < n) p[i] = 0.0f;
}

__global__ void __launch_bounds__(NTHR, 1)
stdp_main_kernel(const float* __restrict__ gin,   // [T, B, N_IN]
                 const float* __restrict__ gout,  // [T, B, N_OUT]
                 float* __restrict__ dw)          // [N_OUT, N_IN]
{
    extern __shared__ __align__(1024) char smem[];
    const uint32_t sb = smem_u32(smem);
    const int tid = threadIdx.x;
    const int w   = tid >> 5;
    const int l   = tid & 31;

    const int t0  = (blockIdx.x * T_STEPS) / GT;
    const int t1  = ((blockIdx.x + 1) * T_STEPS) / GT;
    const int len = t1 - t0;                 // 55 or 56
    const int b0  = blockIdx.y * KB;

    // ---- per-thread offsets -------------------------------------------------
    // in:  f = tid + 512q, q<4;  b = f>>6, i = (f&63)*4
    // out: f = tid + 512q, q<2;  b = f>>5, o = (f&31)*4
    int gi_off[4]; uint32_t si_slot[4]; uint32_t sts_in[4];
#pragma unroll
    for (int q = 0; q < 4; q++) {
        int f  = tid + 512 * q;
        int bl = f >> 6;
        int i4 = (f & 63) << 2;
        gi_off[q]  = ((b0 + bl) * (N_IN / 4) + (f & 63)) * 16;
        si_slot[q] = (uint32_t)(f * 16);
        sts_in[q]  = (uint32_t)(bl * 512 + (((i4 >> 3) ^ (bl & 7)) << 4) + ((i4 & 7) << 1));
    }
    int go_off[2]; uint32_t sts_out[2];
#pragma unroll
    for (int q = 0; q < 2; q++) {
        int f  = tid + 512 * q;
        int bl = f >> 5;
        int o4 = (f & 31) << 2;
        go_off[q]  = (b0 + bl) * (N_OUT / 4) + (f & 31);
        sts_out[q] = (uint32_t)(bl * 256 + (((o4 >> 3) ^ (bl & 7)) << 4) + ((o4 & 7) << 1));
    }

    // ---- ldmatrix source addresses (relative to tile buf base) --------------
    const int wr = w >> 2, wc = w & 3;
    const int obase = wr * 32, ibase = wc * 64;

    uint32_t a_addr[2];
#pragma unroll
    for (int mt = 0; mt < 2; mt++) {
        int b  = (l & 7) + ((l >> 4) << 3);
        int ch = ((obase + mt * 16) >> 3) + ((l >> 3) & 1);
        a_addr[mt] = (uint32_t)(b * 256 + ((ch ^ (b & 7)) << 4));
    }
    uint32_t b_addr[4];
#pragma unroll
    for (int np = 0; np < 4; np++) {
        int b  = (l & 7) + (((l >> 3) & 1) << 3);
        int ch = ((ibase + np * 16) >> 3) + ((l >> 4) & 1);
        b_addr[np] = (uint32_t)(b * 512 + ((ch ^ (b & 7)) << 4));
    }

    // ---- prologue staging: steps t0..t0+3, one group per step ---------------
#pragma unroll
    for (int p = 0; p < 4; p++) {
        const char* src = (const char*)gin + (size_t)(t0 + p) * IN_SLAB;
#pragma unroll
        for (int q = 0; q < 4; q++)
            cp16(sb + p * SI_STEP + si_slot[q], src + gi_off[q]);
        CP_COMMIT();
    }

    // ---- trace warm-up (overlaps staging) -----------------------------------
    float4 tr4[4];
#pragma unroll
    for (int q = 0; q < 4; q++) tr4[q] = make_float4(0.f, 0.f, 0.f, 0.f);

    int tw0 = t0 - WARMUP; if (tw0 < 0) tw0 = 0;
#pragma unroll 2
    for (int t = tw0; t < t0; t++) {
        const char* src = (const char*)gin + (size_t)t * IN_SLAB;
#pragma unroll
        for (int q = 0; q < 4; q++) {
            float4 v = *reinterpret_cast<const float4*>(src + gi_off[q]);
            tr4[q].x = fmaf(0.5f, tr4[q].x, v.x);
            tr4[q].y = fmaf(0.5f, tr4[q].y, v.y);
            tr4[q].z = fmaf(0.5f, tr4[q].z, v.z);
            tr4[q].w = fmaf(0.5f, tr4[q].w, v.w);
        }
    }

    float acc[2][8][4];
#pragma unroll
    for (int mt = 0; mt < 2; mt++)
#pragma unroll
        for (int nt = 0; nt < 8; nt++)
#pragma unroll
            for (int r = 0; r < 4; r++) acc[mt][nt][r] = 0.0f;

    // out values for the step about to be produced
    float4 voA[2];
    {
        const float4* po = reinterpret_cast<const float4*>(gout) + (size_t)t0 * OUT_SLAB;
#pragma unroll
        for (int q = 0; q < 2; q++) voA[q] = po[go_off[q]];
    }

    // produce(sp): build bf16 tiles for step sp, refill staging with sp+4,
    // prefetch out for sp+1. Assumes voA holds out(sp) on entry.
    auto produce = [&](int sp) {
        const int slot = sp & 3;
        const int buf  = sp & 1;
        CP_WAIT3();   // staging slot for step sp complete
        const char* sg = smem + slot * SI_STEP;
        char* td = smem + TR_OFF + buf * TR_BSZ;
#pragma unroll
        for (int q = 0; q < 4; q++) {
            float4 v = *reinterpret_cast<const float4*>(sg + si_slot[q]);
            tr4[q].x = fmaf(0.5f, tr4[q].x, v.x);
            tr4[q].y = fmaf(0.5f, tr4[q].y, v.y);
            tr4[q].z = fmaf(0.5f, tr4[q].z, v.z);
            tr4[q].w = fmaf(0.5f, tr4[q].w, v.w);
            uint2 u = make_uint2(pack_bf16x2(tr4[q].x, tr4[q].y),
                                 pack_bf16x2(tr4[q].z, tr4[q].w));
            *reinterpret_cast<uint2*>(td + sts_in[q]) = u;
        }
        char* od = smem + OT_OFF + buf * OT_BSZ;
#pragma unroll
        for (int q = 0; q < 2; q++) {
            uint2 u = make_uint2(pack_bf16x2(voA[q].x, voA[q].y),
                                 pack_bf16x2(voA[q].z, voA[q].w));
            *reinterpret_cast<uint2*>(od + sts_out[q]) = u;
        }
        // prefetch out(sp+1) (consumed by produce(sp+1), one iteration later)
        if (sp + 1 < len) {
            const float4* po = reinterpret_cast<const float4*>(gout)
                             + (size_t)(t0 + sp + 1) * OUT_SLAB;
#pragma unroll
            for (int q = 0; q < 2; q++) voA[q] = po[go_off[q]];
        }
        // refill this slot with step sp+4 (slot bytes self-consumed above)
        if (sp + 4 < len) {
            const char* src = (const char*)gin + (size_t)(t0 + sp + 4) * IN_SLAB;
#pragma unroll
            for (int q = 0; q < 4; q++) cp16(sb + slot * SI_STEP + si_slot[q], src + gi_off[q]);
        }
        CP_COMMIT();
    };

    auto do_mma = [&](int buf) {
        const uint32_t abase = sb + OT_OFF + buf * OT_BSZ;
        const uint32_t bbase = sb + TR_OFF + buf * TR_BSZ;
#pragma unroll
        for (int kb = 0; kb < 2; kb++) {
            uint32_t af[2][4];
            ldsm4t(af[0], abase + a_addr[0] + kb * 16 * 256);
            ldsm4t(af[1], abase + a_addr[1] + kb * 16 * 256);
#pragma unroll
            for (int np = 0; np < 4; np++) {
                uint32_t bf[4];
                ldsm4t(bf, bbase + b_addr[np] + kb * 16 * 512);
#pragma unroll
                for (int mt = 0; mt < 2; mt++) {
                    mma16816(acc[mt][2 * np],     af[mt], bf);
                    mma16816(acc[mt][2 * np + 1], af[mt], bf + 2);
                }
            }
        }
    };

    // build tiles for step 0, then pipelined main loop
    produce(0);
    __syncthreads();

    for (int s = 0; s < len; s++) {
        if ((w & 1) == 0) {
            do_mma(s & 1);
            if (s + 1 < len) produce(s + 1);
        } else {
            if (s + 1 < len) produce(s + 1);
            do_mma(s & 1);
        }
        __syncthreads();
    }

    // ---- epilogue: vector reductions into dw --------------------------------
#pragma unroll
    for (int mt = 0; mt < 2; mt++) {
#pragma unroll
        for (int nt = 0; nt < 8; nt++) {
            const int o = obase + mt * 16 + (l >> 2);
            const int i = ibase + nt * 8 + ((l & 3) << 1);
            float* p = dw + (size_t)o * N_IN + i;
            asm volatile("red.global.add.v2.f32 [%0], {%1,%2};"
                         :: "l"(p), "f"(acc[mt][nt][0]), "f"(acc[mt][nt][1]) : "memory");
            asm volatile("red.global.add.v2.f32 [%0], {%1,%2};"
                         :: "l"(p + 8 * N_IN), "f"(acc[mt][nt][2]), "f"(acc[mt][nt][3]) : "memory");
        }
    }
}

extern "C" void kernel_launch(void* const* d_in, const int* in_sizes, int n_in,
                              void* d_out, int out_size) {
    (void)in_sizes; (void)n_in; (void)out_size;
    const float* gin  = (const float*)d_in[0];   // in_spikes  [T, B, N_IN]
    const float* gout = (const float*)d_in[1];   // out_spikes [T, B, N_OUT]
    float* dw = (float*)d_out;                   // [N_OUT, N_IN]

    stdp_zero_kernel<<<(N_OUT * N_IN + NTHR - 1) / NTHR, NTHR>>>(dw, N_OUT * N_IN);

    cudaFuncSetAttribute(stdp_main_kernel,
                         cudaFuncAttributeMaxDynamicSharedMemorySize, SM_TOTAL);
    dim3 grid(GT, NBS);
    stdp_main_kernel<<<grid, NTHR, SM_TOTAL>>>(gin, gout, dw);
}